// round 4
// baseline (speedup 1.0000x reference)
#include <cuda_runtime.h>
#include <math.h>

// Problem dims (fixed)
#define BB   2
#define TT   2048
#define DD   2048
#define HH   16
#define HD   128
#define FF   4096
#define MTOK 4096            // B*T
#define QKVW (3*DD)          // 6144

// ---------------- scratch (static __device__, no allocations) ----------------
__device__ float g_h   [(size_t)MTOK * DD];    // normed activations
__device__ float g_qkv [(size_t)MTOK * QKVW];  // qkv projections
__device__ float g_attn[(size_t)MTOK * DD];    // attention output
__device__ float g_x1  [(size_t)MTOK * DD];    // x after attention residual
__device__ float g_gate[(size_t)MTOK * FF];    // gate proj / ff buffer
__device__ float g_up  [(size_t)MTOK * FF];    // up proj

// ---------------- RMSNorm * w * gamma + beta ----------------
__global__ void __launch_bounds__(256) rmsnorm_affine_kernel(
    const float* __restrict__ x, const float* __restrict__ w,
    const float* __restrict__ gamma, const float* __restrict__ beta,
    float* __restrict__ out)
{
    const int row = blockIdx.x;
    const float4* xr = (const float4*)(x + (size_t)row * DD);
    const int t = threadIdx.x;

    float4 v0 = xr[t];
    float4 v1 = xr[t + 256];
    float ss = v0.x*v0.x + v0.y*v0.y + v0.z*v0.z + v0.w*v0.w
             + v1.x*v1.x + v1.y*v1.y + v1.z*v1.z + v1.w*v1.w;
    #pragma unroll
    for (int d = 16; d; d >>= 1) ss += __shfl_xor_sync(0xffffffffu, ss, d);
    __shared__ float red[8];
    if ((t & 31) == 0) red[t >> 5] = ss;
    __syncthreads();
    float tot = red[0] + red[1] + red[2] + red[3] + red[4] + red[5] + red[6] + red[7];
    const float inv = rsqrtf(tot * (1.0f / DD) + 1.1920929e-07f);

    const float4* w4 = (const float4*)w;
    const float4* g4 = (const float4*)gamma;
    const float4* b4 = (const float4*)beta;
    float4* orow = (float4*)(out + (size_t)row * DD);
    #pragma unroll
    for (int c = 0; c < 2; ++c) {
        int i = t + c * 256;
        float4 xv = (c == 0) ? v0 : v1;
        float4 wv = w4[i], gv = g4[i], bv = b4[i];
        float4 o;
        o.x = xv.x * inv * wv.x * gv.x + bv.x;
        o.y = xv.y * inv * wv.y * gv.y + bv.y;
        o.z = xv.z * inv * wv.z * gv.z + bv.z;
        o.w = xv.w * inv * wv.w * gv.w + bv.w;
        orow[i] = o;
    }
}

// ---------------- SGEMM: C[M,N] = A[M,K] @ B[N,K]^T (+ res) ----------------
// 128x128 block tile, Ktile=8, 256 threads, 8x8 per thread (stride-16 mapping).
template<bool RES>
__global__ void __launch_bounds__(256, 2) sgemm_nt_kernel(
    const float* __restrict__ A, const float* __restrict__ B,
    const float* __restrict__ res, float* __restrict__ C,
    int M, int N, int K)
{
    __shared__ float As[8][129];
    __shared__ float Bs[8][129];
    const int tid = threadIdx.x;
    const int tx = tid & 15, ty = tid >> 4;
    const int row0 = blockIdx.y << 7, col0 = blockIdx.x << 7;
    const int lrow = tid >> 1;
    const int lk = (tid & 1) << 2;
    const float* Ap = A + (size_t)(row0 + lrow) * K + lk;
    const float* Bp = B + (size_t)(col0 + lrow) * K + lk;

    float acc[8][8];
    #pragma unroll
    for (int i = 0; i < 8; ++i)
        #pragma unroll
        for (int j = 0; j < 8; ++j) acc[i][j] = 0.f;

    const int nk = K >> 3;
    float4 pa = *(const float4*)Ap;
    float4 pb = *(const float4*)Bp;

    for (int kt = 0; kt < nk; ++kt) {
        As[lk+0][lrow] = pa.x; As[lk+1][lrow] = pa.y; As[lk+2][lrow] = pa.z; As[lk+3][lrow] = pa.w;
        Bs[lk+0][lrow] = pb.x; Bs[lk+1][lrow] = pb.y; Bs[lk+2][lrow] = pb.z; Bs[lk+3][lrow] = pb.w;
        __syncthreads();
        if (kt + 1 < nk) {
            pa = *(const float4*)(Ap + ((size_t)(kt + 1) << 3));
            pb = *(const float4*)(Bp + ((size_t)(kt + 1) << 3));
        }
        #pragma unroll
        for (int kk = 0; kk < 8; ++kk) {
            float a[8], b[8];
            #pragma unroll
            for (int i = 0; i < 8; ++i) a[i] = As[kk][ty + (i << 4)];
            #pragma unroll
            for (int j = 0; j < 8; ++j) b[j] = Bs[kk][tx + (j << 4)];
            #pragma unroll
            for (int i = 0; i < 8; ++i)
                #pragma unroll
                for (int j = 0; j < 8; ++j)
                    acc[i][j] = fmaf(a[i], b[j], acc[i][j]);
        }
        __syncthreads();
    }

    #pragma unroll
    for (int i = 0; i < 8; ++i) {
        const size_t r = (size_t)(row0 + ty + (i << 4));
        #pragma unroll
        for (int j = 0; j < 8; ++j) {
            const size_t c = (size_t)(col0 + tx + (j << 4));
            float v = acc[i][j];
            if (RES) v += res[r * N + c];
            C[r * N + c] = v;
        }
    }
}

// ---------------- causal flash attention (fp32) ----------------
// grid: (T/64 q-tiles, B*H). 256 threads. BR=BC=64, HD=128.
// thread (tx,ty): rows ty*4+i (i<4), cols tx+16*cc (cc<8).
#define FLASH_SMEM ((64*128 + 2*64*129 + 64*65) * 4)

__global__ void __launch_bounds__(256) flash_attn_kernel(
    const float* __restrict__ qkv, float* __restrict__ out)
{
    const int qt = blockIdx.x;
    const int bh = blockIdx.y;
    const int b = bh >> 4, h = bh & 15;
    extern __shared__ float smf[];
    float* Qs = smf;                 // [64][128]
    float* Ks = Qs + 64 * 128;       // [64][129]
    float* Vs = Ks + 64 * 129;       // [64][129]
    float* Ss = Vs + 64 * 129;       // [64][65]
    const int tid = threadIdx.x;
    const int tx = tid & 15, ty = tid >> 4;
    const float scale = 0.08838834764831845f;  // 1/sqrt(128)

    const float* base = qkv + (size_t)b * TT * QKVW + (size_t)h * HD;

    // load Q (pre-scaled)
    #pragma unroll
    for (int it = 0; it < 8; ++it) {
        int idx = tid + (it << 8);           // 0..2047 float4s
        int r = idx >> 5, c4 = idx & 31;
        float4 v = *(const float4*)(base + (size_t)(qt * 64 + r) * QKVW + (c4 << 2));
        v.x *= scale; v.y *= scale; v.z *= scale; v.w *= scale;
        *(float4*)(Qs + r * 128 + (c4 << 2)) = v;
    }

    float acc[4][8];
    #pragma unroll
    for (int i = 0; i < 4; ++i)
        #pragma unroll
        for (int c = 0; c < 8; ++c) acc[i][c] = 0.f;
    float mrow[4], lsum[4];
    #pragma unroll
    for (int i = 0; i < 4; ++i) { mrow[i] = -INFINITY; lsum[i] = 0.f; }

    for (int jt = 0; jt <= qt; ++jt) {
        __syncthreads();  // prior PV reads done; Q visible on first iter
        // load K,V tiles
        #pragma unroll
        for (int it = 0; it < 8; ++it) {
            int idx = tid + (it << 8);
            int r = idx >> 5, c4 = idx & 31;
            const float* kp = base + DD + (size_t)(jt * 64 + r) * QKVW + (c4 << 2);
            float4 kv = *(const float4*)kp;
            float* kd = Ks + r * 129 + (c4 << 2);
            kd[0] = kv.x; kd[1] = kv.y; kd[2] = kv.z; kd[3] = kv.w;
            float4 vv = *(const float4*)(kp + DD);
            float* vd = Vs + r * 129 + (c4 << 2);
            vd[0] = vv.x; vd[1] = vv.y; vd[2] = vv.z; vd[3] = vv.w;
        }
        __syncthreads();

        // S = Q K^T  (4x4 per thread, cols tx+16*jj)
        float s[4][4];
        #pragma unroll
        for (int i = 0; i < 4; ++i)
            #pragma unroll
            for (int j = 0; j < 4; ++j) s[i][j] = 0.f;
        #pragma unroll 8
        for (int kk = 0; kk < 128; ++kk) {
            float q[4], k[4];
            #pragma unroll
            for (int i = 0; i < 4; ++i) q[i] = Qs[(ty * 4 + i) * 128 + kk];
            #pragma unroll
            for (int j = 0; j < 4; ++j) k[j] = Ks[(tx + (j << 4)) * 129 + kk];
            #pragma unroll
            for (int i = 0; i < 4; ++i)
                #pragma unroll
                for (int j = 0; j < 4; ++j)
                    s[i][j] = fmaf(q[i], k[j], s[i][j]);
        }
        if (jt == qt) {
            #pragma unroll
            for (int i = 0; i < 4; ++i)
                #pragma unroll
                for (int j = 0; j < 4; ++j)
                    if ((tx + (j << 4)) > (ty * 4 + i)) s[i][j] = -INFINITY;
        }

        // online softmax (row stats via 16-lane shfl reduce)
        #pragma unroll
        for (int i = 0; i < 4; ++i) {
            float mx = fmaxf(fmaxf(s[i][0], s[i][1]), fmaxf(s[i][2], s[i][3]));
            #pragma unroll
            for (int d = 8; d; d >>= 1) mx = fmaxf(mx, __shfl_xor_sync(0xffffffffu, mx, d));
            float mnew = fmaxf(mrow[i], mx);
            float alpha = __expf(mrow[i] - mnew);
            mrow[i] = mnew;
            float p[4], ps = 0.f;
            #pragma unroll
            for (int j = 0; j < 4; ++j) { p[j] = __expf(s[i][j] - mnew); ps += p[j]; }
            #pragma unroll
            for (int d = 8; d; d >>= 1) ps += __shfl_xor_sync(0xffffffffu, ps, d);
            lsum[i] = lsum[i] * alpha + ps;
            #pragma unroll
            for (int c = 0; c < 8; ++c) acc[i][c] *= alpha;
            #pragma unroll
            for (int j = 0; j < 4; ++j) Ss[(ty * 4 + i) * 65 + tx + (j << 4)] = p[j];
        }
        __syncthreads();

        // O += P @ V
        #pragma unroll 4
        for (int j = 0; j < 64; ++j) {
            float vv[8];
            #pragma unroll
            for (int c = 0; c < 8; ++c) vv[c] = Vs[j * 129 + tx + (c << 4)];
            #pragma unroll
            for (int i = 0; i < 4; ++i) {
                float p = Ss[(ty * 4 + i) * 65 + j];
                #pragma unroll
                for (int c = 0; c < 8; ++c) acc[i][c] = fmaf(p, vv[c], acc[i][c]);
            }
        }
    }

    // write O / l  -> (B,T,D) with head-major layout
    #pragma unroll
    for (int i = 0; i < 4; ++i) {
        float invl = 1.0f / lsum[i];
        size_t orow = (size_t)(b * TT + qt * 64 + ty * 4 + i) * DD + (size_t)h * HD;
        #pragma unroll
        for (int c = 0; c < 8; ++c)
            out[orow + tx + (c << 4)] = acc[i][c] * invl;
    }
}

// ---------------- silu(gate) * up ----------------
__global__ void __launch_bounds__(256) silu_mul_kernel(
    const float* __restrict__ g, const float* __restrict__ u,
    float* __restrict__ o, int n4)
{
    int i = blockIdx.x * blockDim.x + threadIdx.x;
    if (i < n4) {
        float4 gv = ((const float4*)g)[i];
        float4 uv = ((const float4*)u)[i];
        float4 r;
        r.x = gv.x / (1.f + __expf(-gv.x)) * uv.x;
        r.y = gv.y / (1.f + __expf(-gv.y)) * uv.y;
        r.z = gv.z / (1.f + __expf(-gv.z)) * uv.z;
        r.w = gv.w / (1.f + __expf(-gv.w)) * uv.w;
        ((float4*)o)[i] = r;
    }
}

// ---------------- launch ----------------
extern "C" void kernel_launch(void* const* d_in, const int* in_sizes, int n_in,
                              void* d_out, int out_size)
{
    const float* x      = (const float*)d_in[0];
    const float* gamma  = (const float*)d_in[1];
    const float* beta   = (const float*)d_in[2];
    const float* qkv_w  = (const float*)d_in[3];
    const float* o_w    = (const float*)d_in[4];
    const float* gate_w = (const float*)d_in[5];
    const float* up_w   = (const float*)d_in[6];
    const float* down_w = (const float*)d_in[7];
    const float* n1w    = (const float*)d_in[8];
    const float* n2w    = (const float*)d_in[9];
    float* out = (float*)d_out;

    float *h_, *qkv_, *attn_, *x1_, *gate_, *up_;
    cudaGetSymbolAddress((void**)&h_,    g_h);
    cudaGetSymbolAddress((void**)&qkv_,  g_qkv);
    cudaGetSymbolAddress((void**)&attn_, g_attn);
    cudaGetSymbolAddress((void**)&x1_,   g_x1);
    cudaGetSymbolAddress((void**)&gate_, g_gate);
    cudaGetSymbolAddress((void**)&up_,   g_up);

    cudaFuncSetAttribute(flash_attn_kernel,
                         cudaFuncAttributeMaxDynamicSharedMemorySize, FLASH_SMEM);

    // 1. h = rmsnorm(x, n1) * gamma + beta
    rmsnorm_affine_kernel<<<MTOK, 256>>>(x, n1w, gamma, beta, h_);
    // 2. qkv = h @ qkv_w^T
    sgemm_nt_kernel<false><<<dim3(QKVW / 128, MTOK / 128), 256>>>(h_, qkv_w, nullptr, qkv_, MTOK, QKVW, DD);
    // 3. attention
    flash_attn_kernel<<<dim3(TT / 64, BB * HH), 256, FLASH_SMEM>>>(qkv_, attn_);
    // 4. x1 = x + attn @ o_w^T
    sgemm_nt_kernel<true><<<dim3(DD / 128, MTOK / 128), 256>>>(attn_, o_w, x, x1_, MTOK, DD, DD);
    // 5. h = rmsnorm(x1, n2) * gamma + beta
    rmsnorm_affine_kernel<<<MTOK, 256>>>(x1_, n2w, gamma, beta, h_);
    // 6/7. gate, up
    sgemm_nt_kernel<false><<<dim3(FF / 128, MTOK / 128), 256>>>(h_, gate_w, nullptr, gate_, MTOK, FF, DD);
    sgemm_nt_kernel<false><<<dim3(FF / 128, MTOK / 128), 256>>>(h_, up_w, nullptr, up_, MTOK, FF, DD);
    // 8. ff = silu(gate) * up   (in place into gate_)
    silu_mul_kernel<<<(MTOK * FF / 4 + 255) / 256, 256>>>(gate_, up_, gate_, MTOK * FF / 4);
    // 9. out = x1 + ff @ down_w^T
    sgemm_nt_kernel<true><<<dim3(DD / 128, MTOK / 128), 256>>>(gate_, down_w, x1_, out, MTOK, DD, FF);
}

// round 7
// speedup vs baseline: 1.5028x; 1.5028x over previous
#include <cuda_runtime.h>
#include <cuda_bf16.h>
#include <math.h>
#include <stdint.h>

// Problem dims (fixed)
#define BB   2
#define TT   2048
#define DD   2048
#define HH   16
#define HD   128
#define FF   4096
#define MTOK 4096            // B*T
#define QKVW (3*DD)          // 6144

// ---------------- scratch (static __device__, no allocations) ----------------
__device__ float g_qkv [(size_t)MTOK * QKVW];  // qkv projections (fp32, for attention)
__device__ float g_x1  [(size_t)MTOK * DD];    // x after attention residual
__device__ float g_gate[(size_t)MTOK * FF];    // gate proj (fp32)
__device__ float g_up  [(size_t)MTOK * FF];    // up proj (fp32)

// bf16 hi/lo activation operand (reused: h1 -> attn-out -> h2 -> ff)
__device__ __nv_bfloat16 g_act_hi[(size_t)MTOK * FF];
__device__ __nv_bfloat16 g_act_lo[(size_t)MTOK * FF];

// bf16 hi/lo weights (converted every launch)
__device__ __nv_bfloat16 g_wqkv_hi[(size_t)QKVW * DD];
__device__ __nv_bfloat16 g_wqkv_lo[(size_t)QKVW * DD];
__device__ __nv_bfloat16 g_wo_hi  [(size_t)DD * DD];
__device__ __nv_bfloat16 g_wo_lo  [(size_t)DD * DD];
__device__ __nv_bfloat16 g_wg_hi  [(size_t)FF * DD];
__device__ __nv_bfloat16 g_wg_lo  [(size_t)FF * DD];
__device__ __nv_bfloat16 g_wu_hi  [(size_t)FF * DD];
__device__ __nv_bfloat16 g_wu_lo  [(size_t)FF * DD];
__device__ __nv_bfloat16 g_wd_hi  [(size_t)DD * FF];
__device__ __nv_bfloat16 g_wd_lo  [(size_t)DD * FF];

// ======================= PTX helpers (baseline ISA only) =======================
__device__ __forceinline__ uint32_t smem_u32(const void* p) {
    uint32_t a;
    asm("{ .reg .u64 t; cvta.to.shared.u64 t, %1; cvt.u32.u64 %0, t; }" : "=r"(a) : "l"(p));
    return a;
}
__device__ __forceinline__ void cp_async16(uint32_t s, const void* g) {
    asm volatile("cp.async.cg.shared.global [%0], [%1], 16;" :: "r"(s), "l"(g));
}
__device__ __forceinline__ void cp_commit() { asm volatile("cp.async.commit_group;" ::: "memory"); }
#define CP_WAIT(n) asm volatile("cp.async.wait_group %0;" :: "n"(n) : "memory")

__device__ __forceinline__ void ldsm4(uint32_t* r, uint32_t addr) {
    asm volatile("ldmatrix.sync.aligned.m8n8.x4.shared.b16 {%0,%1,%2,%3}, [%4];"
        : "=r"(r[0]), "=r"(r[1]), "=r"(r[2]), "=r"(r[3]) : "r"(addr));
}
__device__ __forceinline__ void mma_bf16(float* d, const uint32_t* a, const uint32_t* b) {
    asm volatile("mma.sync.aligned.m16n8k16.row.col.f32.bf16.bf16.f32 "
        "{%0,%1,%2,%3}, {%4,%5,%6,%7}, {%8,%9}, {%0,%1,%2,%3};"
        : "+f"(d[0]), "+f"(d[1]), "+f"(d[2]), "+f"(d[3])
        : "r"(a[0]), "r"(a[1]), "r"(a[2]), "r"(a[3]), "r"(b[0]), "r"(b[1]));
}

// ======================= fp32 -> bf16 hi/lo split =======================
__device__ __forceinline__ void split2(float a, float b, __nv_bfloat162* hi, __nv_bfloat162* lo) {
    __nv_bfloat16 ha = __float2bfloat16(a), hb = __float2bfloat16(b);
    *hi = __nv_bfloat162(ha, hb);
    *lo = __nv_bfloat162(__float2bfloat16(a - __bfloat162float(ha)),
                         __float2bfloat16(b - __bfloat162float(hb)));
}

__global__ void __launch_bounds__(256) split_kernel(
    const float* __restrict__ in, __nv_bfloat16* __restrict__ hi,
    __nv_bfloat16* __restrict__ lo, int n4)
{
    int i = blockIdx.x * blockDim.x + threadIdx.x;
    if (i >= n4) return;
    float4 v = ((const float4*)in)[i];
    __nv_bfloat162 h0, l0, h1, l1;
    split2(v.x, v.y, &h0, &l0);
    split2(v.z, v.w, &h1, &l1);
    ((__nv_bfloat162*)hi)[2 * i]     = h0;
    ((__nv_bfloat162*)hi)[2 * i + 1] = h1;
    ((__nv_bfloat162*)lo)[2 * i]     = l0;
    ((__nv_bfloat162*)lo)[2 * i + 1] = l1;
}

// ---------------- RMSNorm * w * gamma + beta -> bf16 hi/lo ----------------
__global__ void __launch_bounds__(256) rmsnorm_affine_kernel(
    const float* __restrict__ x, const float* __restrict__ w,
    const float* __restrict__ gamma, const float* __restrict__ beta,
    __nv_bfloat16* __restrict__ ohi, __nv_bfloat16* __restrict__ olo)
{
    const int row = blockIdx.x;
    const float4* xr = (const float4*)(x + (size_t)row * DD);
    const int t = threadIdx.x;

    float4 v0 = xr[t];
    float4 v1 = xr[t + 256];
    float ss = v0.x*v0.x + v0.y*v0.y + v0.z*v0.z + v0.w*v0.w
             + v1.x*v1.x + v1.y*v1.y + v1.z*v1.z + v1.w*v1.w;
    #pragma unroll
    for (int d = 16; d; d >>= 1) ss += __shfl_xor_sync(0xffffffffu, ss, d);
    __shared__ float red[8];
    if ((t & 31) == 0) red[t >> 5] = ss;
    __syncthreads();
    float tot = red[0] + red[1] + red[2] + red[3] + red[4] + red[5] + red[6] + red[7];
    const float inv = rsqrtf(tot * (1.0f / DD) + 1.1920929e-07f);

    const float4* w4 = (const float4*)w;
    const float4* g4 = (const float4*)gamma;
    const float4* b4 = (const float4*)beta;
    __nv_bfloat162* oh = (__nv_bfloat162*)(ohi + (size_t)row * DD);
    __nv_bfloat162* ol = (__nv_bfloat162*)(olo + (size_t)row * DD);
    #pragma unroll
    for (int c = 0; c < 2; ++c) {
        int i = t + c * 256;
        float4 xv = (c == 0) ? v0 : v1;
        float4 wv = w4[i], gv = g4[i], bv = b4[i];
        float4 o;
        o.x = xv.x * inv * wv.x * gv.x + bv.x;
        o.y = xv.y * inv * wv.y * gv.y + bv.y;
        o.z = xv.z * inv * wv.z * gv.z + bv.z;
        o.w = xv.w * inv * wv.w * gv.w + bv.w;
        __nv_bfloat162 h0, l0, h1, l1;
        split2(o.x, o.y, &h0, &l0);
        split2(o.z, o.w, &h1, &l1);
        oh[2 * i] = h0; oh[2 * i + 1] = h1;
        ol[2 * i] = l0; ol[2 * i + 1] = l1;
    }
}

// ======================= mma.sync GEMM =======================
// C[M,N] = A[M,K] @ B[N,K]^T (+res). A/B bf16 hi/lo pairs, fp32 reg accum.
// CTA tile 128x128, BK=32, 8 warps (2M x 4N), warp tile 64x32.
// 3 HMMA terms per k16: Ah*Bh + Ah*Bl + Al*Bh.
#define BKC 32
#define STG 3
#define STAGE_B 32768
#define OFF_AH 0
#define OFF_AL 8192
#define OFF_BH 16384
#define OFF_BL 24576
#define GEMM_SMEM (STG * STAGE_B)

// swizzled byte offset for (row, 16B-unit u) in a [128][32]bf16 tile (64B rows)
#define SWZ(r_, u_) ((uint32_t)(r_) * 64u + ((((uint32_t)(u_)) ^ (((uint32_t)(r_) >> 1) & 3u)) << 4))

template<bool RES>
__global__ void __launch_bounds__(256) gemm_mma_kernel(
    const __nv_bfloat16* __restrict__ Ahi, const __nv_bfloat16* __restrict__ Alo,
    const __nv_bfloat16* __restrict__ Bhi, const __nv_bfloat16* __restrict__ Blo,
    const float* __restrict__ res, float* __restrict__ C, int N, int K)
{
    extern __shared__ char smraw[];
    const uint32_t sb = smem_u32(smraw);
    const int tid  = threadIdx.x;
    const int lane = tid & 31;
    const int warp = tid >> 5;
    const int wm = warp >> 2, wn = warp & 3;
    const int row0 = blockIdx.y << 7;
    const int col0 = blockIdx.x << 7;

    // ---- loader mapping: thread t -> (row lr & lr+64, 16B-unit lu) ----
    const int lr = tid >> 2, lu = tid & 3;
    const uint32_t wsw0 = SWZ(lr, lu);
    const uint32_t wsw1 = SWZ(lr + 64, lu);
    const size_t rK64 = (size_t)64 * K;
    const __nv_bfloat16* gAh = Ahi + (size_t)(row0 + lr) * K + lu * 8;
    const __nv_bfloat16* gAl = Alo + (size_t)(row0 + lr) * K + lu * 8;
    const __nv_bfloat16* gBh = Bhi + (size_t)(col0 + lr) * K + lu * 8;
    const __nv_bfloat16* gBl = Blo + (size_t)(col0 + lr) * K + lu * 8;

#define LOAD_STAGE(kt_, st_) do {                                   \
    uint32_t b_ = sb + (uint32_t)(st_) * STAGE_B;                   \
    size_t ko_ = (size_t)(kt_) * BKC;                               \
    cp_async16(b_ + OFF_AH + wsw0, gAh + ko_);                      \
    cp_async16(b_ + OFF_AH + wsw1, gAh + rK64 + ko_);               \
    cp_async16(b_ + OFF_AL + wsw0, gAl + ko_);                      \
    cp_async16(b_ + OFF_AL + wsw1, gAl + rK64 + ko_);               \
    cp_async16(b_ + OFF_BH + wsw0, gBh + ko_);                      \
    cp_async16(b_ + OFF_BH + wsw1, gBh + rK64 + ko_);               \
    cp_async16(b_ + OFF_BL + wsw0, gBl + ko_);                      \
    cp_async16(b_ + OFF_BL + wsw1, gBl + rK64 + ko_);               \
    cp_commit();                                                    \
} while (0)

    // ---- ldmatrix per-lane smem offsets ----
    const int m8 = lane >> 3;
    uint32_t offA[4][2], offB[2][2];
    #pragma unroll
    for (int i = 0; i < 4; ++i)
        #pragma unroll
        for (int kc = 0; kc < 2; ++kc) {
            int rowa = wm * 64 + i * 16 + ((m8 & 1) << 3) + (lane & 7);
            int ua = kc * 2 + (m8 >> 1);
            offA[i][kc] = SWZ(rowa, ua);
        }
    #pragma unroll
    for (int j = 0; j < 2; ++j)
        #pragma unroll
        for (int kc = 0; kc < 2; ++kc) {
            int nb = wn * 32 + j * 16 + ((m8 >> 1) << 3) + (lane & 7);
            int ub = kc * 2 + (m8 & 1);
            offB[j][kc] = SWZ(nb, ub);
        }

    float acc[4][4][4];
    #pragma unroll
    for (int i = 0; i < 4; ++i)
        #pragma unroll
        for (int j = 0; j < 4; ++j)
            #pragma unroll
            for (int r = 0; r < 4; ++r) acc[i][j][r] = 0.f;

    const int nk = K / BKC;

    LOAD_STAGE(0, 0);
    LOAD_STAGE(1, 1);

    for (int kt = 0; kt < nk; ++kt) {
        const int st = kt % STG;
        if (kt + 2 < nk) {
            LOAD_STAGE(kt + 2, (kt + 2) % STG);
            CP_WAIT(2);
        } else if (kt + 1 < nk) {
            CP_WAIT(1);
        } else {
            CP_WAIT(0);
        }
        __syncthreads();

        const uint32_t base = sb + (uint32_t)st * STAGE_B;
        #pragma unroll
        for (int kc = 0; kc < 2; ++kc) {
            uint32_t ah[4][4], al[4][4], bh[2][4], bl[2][4];
            #pragma unroll
            for (int i = 0; i < 4; ++i) {
                ldsm4(ah[i], base + OFF_AH + offA[i][kc]);
                ldsm4(al[i], base + OFF_AL + offA[i][kc]);
            }
            #pragma unroll
            for (int j = 0; j < 2; ++j) {
                ldsm4(bh[j], base + OFF_BH + offB[j][kc]);
                ldsm4(bl[j], base + OFF_BL + offB[j][kc]);
            }
            #pragma unroll
            for (int i = 0; i < 4; ++i)
                #pragma unroll
                for (int jf = 0; jf < 4; ++jf) {
                    const uint32_t* bhp = &bh[jf >> 1][(jf & 1) * 2];
                    const uint32_t* blp = &bl[jf >> 1][(jf & 1) * 2];
                    mma_bf16(acc[i][jf], ah[i], bhp);
                    mma_bf16(acc[i][jf], ah[i], blp);
                    mma_bf16(acc[i][jf], al[i], bhp);
                }
        }
        __syncthreads();
    }

    // ---- epilogue: fragment -> global (+res) ----
    const int er = lane >> 2;          // 0..7
    const int ec = (lane & 3) * 2;     // 0,2,4,6
    #pragma unroll
    for (int i = 0; i < 4; ++i) {
        const int grow = row0 + wm * 64 + i * 16 + er;
        #pragma unroll
        for (int jf = 0; jf < 4; ++jf) {
            const int gcol = col0 + wn * 32 + jf * 8 + ec;
            float2 v0 = make_float2(acc[i][jf][0], acc[i][jf][1]);
            float2 v1 = make_float2(acc[i][jf][2], acc[i][jf][3]);
            if (RES) {
                float2 r0 = *(const float2*)(res + (size_t)grow * N + gcol);
                float2 r1 = *(const float2*)(res + (size_t)(grow + 8) * N + gcol);
                v0.x += r0.x; v0.y += r0.y; v1.x += r1.x; v1.y += r1.y;
            }
            *(float2*)(C + (size_t)grow * N + gcol) = v0;
            *(float2*)(C + (size_t)(grow + 8) * N + gcol) = v1;
        }
    }
#undef LOAD_STAGE
}

// ---------------- causal flash attention (fp32), bf16 hi/lo output ----------------
#define FLASH_SMEM ((64*128 + 2*64*129 + 64*65) * 4)

__global__ void __launch_bounds__(256) flash_attn_kernel(
    const float* __restrict__ qkv,
    __nv_bfloat16* __restrict__ ohi, __nv_bfloat16* __restrict__ olo)
{
    const int qt = blockIdx.x;
    const int bh = blockIdx.y;
    const int b = bh >> 4, h = bh & 15;
    extern __shared__ float smf[];
    float* Qs = smf;                 // [64][128]
    float* Ks = Qs + 64 * 128;       // [64][129]
    float* Vs = Ks + 64 * 129;       // [64][129]
    float* Ss = Vs + 64 * 129;       // [64][65]
    const int tid = threadIdx.x;
    const int tx = tid & 15, ty = tid >> 4;
    const float scale = 0.08838834764831845f;  // 1/sqrt(128)

    const float* base = qkv + (size_t)b * TT * QKVW + (size_t)h * HD;

    #pragma unroll
    for (int it = 0; it < 8; ++it) {
        int idx = tid + (it << 8);
        int r = idx >> 5, c4 = idx & 31;
        float4 v = *(const float4*)(base + (size_t)(qt * 64 + r) * QKVW + (c4 << 2));
        v.x *= scale; v.y *= scale; v.z *= scale; v.w *= scale;
        *(float4*)(Qs + r * 128 + (c4 << 2)) = v;
    }

    float acc[4][8];
    #pragma unroll
    for (int i = 0; i < 4; ++i)
        #pragma unroll
        for (int c = 0; c < 8; ++c) acc[i][c] = 0.f;
    float mrow[4], lsum[4];
    #pragma unroll
    for (int i = 0; i < 4; ++i) { mrow[i] = -INFINITY; lsum[i] = 0.f; }

    for (int jt = 0; jt <= qt; ++jt) {
        __syncthreads();
        #pragma unroll
        for (int it = 0; it < 8; ++it) {
            int idx = tid + (it << 8);
            int r = idx >> 5, c4 = idx & 31;
            const float* kp = base + DD + (size_t)(jt * 64 + r) * QKVW + (c4 << 2);
            float4 kv = *(const float4*)kp;
            float* kd = Ks + r * 129 + (c4 << 2);
            kd[0] = kv.x; kd[1] = kv.y; kd[2] = kv.z; kd[3] = kv.w;
            float4 vv = *(const float4*)(kp + DD);
            float* vd = Vs + r * 129 + (c4 << 2);
            vd[0] = vv.x; vd[1] = vv.y; vd[2] = vv.z; vd[3] = vv.w;
        }
        __syncthreads();

        float s[4][4];
        #pragma unroll
        for (int i = 0; i < 4; ++i)
            #pragma unroll
            for (int j = 0; j < 4; ++j) s[i][j] = 0.f;
        #pragma unroll 8
        for (int kk = 0; kk < 128; ++kk) {
            float q[4], k[4];
            #pragma unroll
            for (int i = 0; i < 4; ++i) q[i] = Qs[(ty * 4 + i) * 128 + kk];
            #pragma unroll
            for (int j = 0; j < 4; ++j) k[j] = Ks[(tx + (j << 4)) * 129 + kk];
            #pragma unroll
            for (int i = 0; i < 4; ++i)
                #pragma unroll
                for (int j = 0; j < 4; ++j)
                    s[i][j] = fmaf(q[i], k[j], s[i][j]);
        }
        if (jt == qt) {
            #pragma unroll
            for (int i = 0; i < 4; ++i)
                #pragma unroll
                for (int j = 0; j < 4; ++j)
                    if ((tx + (j << 4)) > (ty * 4 + i)) s[i][j] = -INFINITY;
        }

        #pragma unroll
        for (int i = 0; i < 4; ++i) {
            float mx = fmaxf(fmaxf(s[i][0], s[i][1]), fmaxf(s[i][2], s[i][3]));
            #pragma unroll
            for (int d = 8; d; d >>= 1) mx = fmaxf(mx, __shfl_xor_sync(0xffffffffu, mx, d));
            float mnew = fmaxf(mrow[i], mx);
            float alpha = __expf(mrow[i] - mnew);
            mrow[i] = mnew;
            float p[4], ps = 0.f;
            #pragma unroll
            for (int j = 0; j < 4; ++j) { p[j] = __expf(s[i][j] - mnew); ps += p[j]; }
            #pragma unroll
            for (int d = 8; d; d >>= 1) ps += __shfl_xor_sync(0xffffffffu, ps, d);
            lsum[i] = lsum[i] * alpha + ps;
            #pragma unroll
            for (int c = 0; c < 8; ++c) acc[i][c] *= alpha;
            #pragma unroll
            for (int j = 0; j < 4; ++j) Ss[(ty * 4 + i) * 65 + tx + (j << 4)] = p[j];
        }
        __syncthreads();

        #pragma unroll 4
        for (int j = 0; j < 64; ++j) {
            float vv[8];
            #pragma unroll
            for (int c = 0; c < 8; ++c) vv[c] = Vs[j * 129 + tx + (c << 4)];
            #pragma unroll
            for (int i = 0; i < 4; ++i) {
                float p = Ss[(ty * 4 + i) * 65 + j];
                #pragma unroll
                for (int c = 0; c < 8; ++c) acc[i][c] = fmaf(p, vv[c], acc[i][c]);
            }
        }
    }

    #pragma unroll
    for (int i = 0; i < 4; ++i) {
        float invl = 1.0f / lsum[i];
        size_t orow = (size_t)(b * TT + qt * 64 + ty * 4 + i) * DD + (size_t)h * HD;
        #pragma unroll
        for (int c = 0; c < 8; ++c) {
            float v = acc[i][c] * invl;
            __nv_bfloat16 hv = __float2bfloat16(v);
            ohi[orow + tx + (c << 4)] = hv;
            olo[orow + tx + (c << 4)] = __float2bfloat16(v - __bfloat162float(hv));
        }
    }
}

// ---------------- silu(gate) * up -> bf16 hi/lo ----------------
__global__ void __launch_bounds__(256) silu_mul_kernel(
    const float* __restrict__ g, const float* __restrict__ u,
    __nv_bfloat16* __restrict__ ohi, __nv_bfloat16* __restrict__ olo, int n4)
{
    int i = blockIdx.x * blockDim.x + threadIdx.x;
    if (i < n4) {
        float4 gv = ((const float4*)g)[i];
        float4 uv = ((const float4*)u)[i];
        float4 r;
        r.x = gv.x / (1.f + __expf(-gv.x)) * uv.x;
        r.y = gv.y / (1.f + __expf(-gv.y)) * uv.y;
        r.z = gv.z / (1.f + __expf(-gv.z)) * uv.z;
        r.w = gv.w / (1.f + __expf(-gv.w)) * uv.w;
        __nv_bfloat162 h0, l0, h1, l1;
        split2(r.x, r.y, &h0, &l0);
        split2(r.z, r.w, &h1, &l1);
        ((__nv_bfloat162*)ohi)[2 * i]     = h0;
        ((__nv_bfloat162*)ohi)[2 * i + 1] = h1;
        ((__nv_bfloat162*)olo)[2 * i]     = l0;
        ((__nv_bfloat162*)olo)[2 * i + 1] = l1;
    }
}

// ---------------- launch ----------------
extern "C" void kernel_launch(void* const* d_in, const int* in_sizes, int n_in,
                              void* d_out, int out_size)
{
    const float* x      = (const float*)d_in[0];
    const float* gamma  = (const float*)d_in[1];
    const float* beta   = (const float*)d_in[2];
    const float* qkv_w  = (const float*)d_in[3];
    const float* o_w    = (const float*)d_in[4];
    const float* gate_w = (const float*)d_in[5];
    const float* up_w   = (const float*)d_in[6];
    const float* down_w = (const float*)d_in[7];
    const float* n1w    = (const float*)d_in[8];
    const float* n2w    = (const float*)d_in[9];
    float* out = (float*)d_out;

    float *qkv_, *x1_, *gate_, *up_;
    __nv_bfloat16 *ahi, *alo, *wqh, *wql, *woh, *wol, *wgh, *wgl, *wuh, *wul, *wdh, *wdl;
    cudaGetSymbolAddress((void**)&qkv_,  g_qkv);
    cudaGetSymbolAddress((void**)&x1_,   g_x1);
    cudaGetSymbolAddress((void**)&gate_, g_gate);
    cudaGetSymbolAddress((void**)&up_,   g_up);
    cudaGetSymbolAddress((void**)&ahi, g_act_hi);
    cudaGetSymbolAddress((void**)&alo, g_act_lo);
    cudaGetSymbolAddress((void**)&wqh, g_wqkv_hi);  cudaGetSymbolAddress((void**)&wql, g_wqkv_lo);
    cudaGetSymbolAddress((void**)&woh, g_wo_hi);    cudaGetSymbolAddress((void**)&wol, g_wo_lo);
    cudaGetSymbolAddress((void**)&wgh, g_wg_hi);    cudaGetSymbolAddress((void**)&wgl, g_wg_lo);
    cudaGetSymbolAddress((void**)&wuh, g_wu_hi);    cudaGetSymbolAddress((void**)&wul, g_wu_lo);
    cudaGetSymbolAddress((void**)&wdh, g_wd_hi);    cudaGetSymbolAddress((void**)&wdl, g_wd_lo);

    cudaFuncSetAttribute(flash_attn_kernel,
                         cudaFuncAttributeMaxDynamicSharedMemorySize, FLASH_SMEM);
    cudaFuncSetAttribute(gemm_mma_kernel<false>,
                         cudaFuncAttributeMaxDynamicSharedMemorySize, GEMM_SMEM);
    cudaFuncSetAttribute(gemm_mma_kernel<true>,
                         cudaFuncAttributeMaxDynamicSharedMemorySize, GEMM_SMEM);

    // 0. split weights to bf16 hi/lo
    {
        int n;
        n = QKVW * DD / 4; split_kernel<<<(n + 255) / 256, 256>>>(qkv_w,  wqh, wql, n);
        n = DD * DD / 4;   split_kernel<<<(n + 255) / 256, 256>>>(o_w,    woh, wol, n);
        n = FF * DD / 4;   split_kernel<<<(n + 255) / 256, 256>>>(gate_w, wgh, wgl, n);
        n = FF * DD / 4;   split_kernel<<<(n + 255) / 256, 256>>>(up_w,   wuh, wul, n);
        n = DD * FF / 4;   split_kernel<<<(n + 255) / 256, 256>>>(down_w, wdh, wdl, n);
    }

    // 1. h = rmsnorm(x, n1)*gamma+beta  -> act (bf16 hi/lo)
    rmsnorm_affine_kernel<<<MTOK, 256>>>(x, n1w, gamma, beta, ahi, alo);
    // 2. qkv = h @ qkv_w^T (fp32 out)
    gemm_mma_kernel<false><<<dim3(QKVW / 128, MTOK / 128), 256, GEMM_SMEM>>>(
        ahi, alo, wqh, wql, nullptr, qkv_, QKVW, DD);
    // 3. attention -> act (bf16 hi/lo)
    flash_attn_kernel<<<dim3(TT / 64, BB * HH), 256, FLASH_SMEM>>>(qkv_, ahi, alo);
    // 4. x1 = x + attn @ o_w^T
    gemm_mma_kernel<true><<<dim3(DD / 128, MTOK / 128), 256, GEMM_SMEM>>>(
        ahi, alo, woh, wol, x, x1_, DD, DD);
    // 5. h = rmsnorm(x1, n2)*gamma+beta -> act
    rmsnorm_affine_kernel<<<MTOK, 256>>>(x1_, n2w, gamma, beta, ahi, alo);
    // 6/7. gate, up (fp32 out)
    gemm_mma_kernel<false><<<dim3(FF / 128, MTOK / 128), 256, GEMM_SMEM>>>(
        ahi, alo, wgh, wgl, nullptr, gate_, FF, DD);
    gemm_mma_kernel<false><<<dim3(FF / 128, MTOK / 128), 256, GEMM_SMEM>>>(
        ahi, alo, wuh, wul, nullptr, up_, FF, DD);
    // 8. ff = silu(gate)*up -> act (bf16 hi/lo, K=FF)
    silu_mul_kernel<<<(MTOK * FF / 4 + 255) / 256, 256>>>(gate_, up_, ahi, alo, MTOK * FF / 4);
    // 9. out = x1 + ff @ down_w^T
    gemm_mma_kernel<true><<<dim3(DD / 128, MTOK / 128), 256, GEMM_SMEM>>>(
        ahi, alo, wdh, wdl, x1_, out, DD, FF);
}

// round 8
// speedup vs baseline: 2.9679x; 1.9750x over previous
#include <cuda_runtime.h>
#include <cuda_bf16.h>
#include <math.h>
#include <stdint.h>

// Problem dims (fixed)
#define BB   2
#define TT   2048
#define DD   2048
#define HH   16
#define HD   128
#define FF   4096
#define MTOK 4096            // B*T
#define QKVW (3*DD)          // 6144

// ---------------- scratch (static __device__, no allocations) ----------------
__device__ float g_x1  [(size_t)MTOK * DD];    // x after attention residual
__device__ float g_gate[(size_t)MTOK * FF];    // gate proj (fp32)
__device__ float g_up  [(size_t)MTOK * FF];    // up proj (fp32)

// bf16 hi/lo activation operand (reused: h1 -> attn-out -> h2 -> ff)
__device__ __nv_bfloat16 g_act_hi[(size_t)MTOK * FF];
__device__ __nv_bfloat16 g_act_lo[(size_t)MTOK * FF];

// qkv hi/lo (written directly by QKV GEMM epilogue)
__device__ __nv_bfloat16 g_qkv_hi[(size_t)MTOK * QKVW];
__device__ __nv_bfloat16 g_qkv_lo[(size_t)MTOK * QKVW];

// bf16 hi/lo weights (converted every launch)
__device__ __nv_bfloat16 g_wqkv_hi[(size_t)QKVW * DD];
__device__ __nv_bfloat16 g_wqkv_lo[(size_t)QKVW * DD];
__device__ __nv_bfloat16 g_wo_hi  [(size_t)DD * DD];
__device__ __nv_bfloat16 g_wo_lo  [(size_t)DD * DD];
__device__ __nv_bfloat16 g_wg_hi  [(size_t)FF * DD];
__device__ __nv_bfloat16 g_wg_lo  [(size_t)FF * DD];
__device__ __nv_bfloat16 g_wu_hi  [(size_t)FF * DD];
__device__ __nv_bfloat16 g_wu_lo  [(size_t)FF * DD];
__device__ __nv_bfloat16 g_wd_hi  [(size_t)DD * FF];
__device__ __nv_bfloat16 g_wd_lo  [(size_t)DD * FF];

// ======================= PTX helpers (baseline ISA only) =======================
__device__ __forceinline__ uint32_t smem_u32(const void* p) {
    uint32_t a;
    asm("{ .reg .u64 t; cvta.to.shared.u64 t, %1; cvt.u32.u64 %0, t; }" : "=r"(a) : "l"(p));
    return a;
}
__device__ __forceinline__ void cp_async16(uint32_t s, const void* g) {
    asm volatile("cp.async.cg.shared.global [%0], [%1], 16;" :: "r"(s), "l"(g));
}
__device__ __forceinline__ void cp_commit() { asm volatile("cp.async.commit_group;" ::: "memory"); }
#define CP_WAIT(n) asm volatile("cp.async.wait_group %0;" :: "n"(n) : "memory")

__device__ __forceinline__ void ldsm4(uint32_t* r, uint32_t addr) {
    asm volatile("ldmatrix.sync.aligned.m8n8.x4.shared.b16 {%0,%1,%2,%3}, [%4];"
        : "=r"(r[0]), "=r"(r[1]), "=r"(r[2]), "=r"(r[3]) : "r"(addr));
}
__device__ __forceinline__ void ldsm4t(uint32_t* r, uint32_t addr) {
    asm volatile("ldmatrix.sync.aligned.m8n8.x4.trans.shared.b16 {%0,%1,%2,%3}, [%4];"
        : "=r"(r[0]), "=r"(r[1]), "=r"(r[2]), "=r"(r[3]) : "r"(addr));
}
__device__ __forceinline__ void mma_bf16(float* d, const uint32_t* a, const uint32_t* b) {
    asm volatile("mma.sync.aligned.m16n8k16.row.col.f32.bf16.bf16.f32 "
        "{%0,%1,%2,%3}, {%4,%5,%6,%7}, {%8,%9}, {%0,%1,%2,%3};"
        : "+f"(d[0]), "+f"(d[1]), "+f"(d[2]), "+f"(d[3])
        : "r"(a[0]), "r"(a[1]), "r"(a[2]), "r"(a[3]), "r"(b[0]), "r"(b[1]));
}

// pack two floats into bf16x2 hi + residual lo
__device__ __forceinline__ void split_pack(float a, float b, uint32_t* hi, uint32_t* lo) {
    __nv_bfloat16 ha = __float2bfloat16(a), hb = __float2bfloat16(b);
    __nv_bfloat16 la = __float2bfloat16(a - __bfloat162float(ha));
    __nv_bfloat16 lb = __float2bfloat16(b - __bfloat162float(hb));
    *hi = ((uint32_t)__bfloat16_as_ushort(hb) << 16) | __bfloat16_as_ushort(ha);
    *lo = ((uint32_t)__bfloat16_as_ushort(lb) << 16) | __bfloat16_as_ushort(la);
}

// ======================= fp32 -> bf16 hi/lo split =======================
__device__ __forceinline__ void split2(float a, float b, __nv_bfloat162* hi, __nv_bfloat162* lo) {
    __nv_bfloat16 ha = __float2bfloat16(a), hb = __float2bfloat16(b);
    *hi = __nv_bfloat162(ha, hb);
    *lo = __nv_bfloat162(__float2bfloat16(a - __bfloat162float(ha)),
                         __float2bfloat16(b - __bfloat162float(hb)));
}

__global__ void __launch_bounds__(256) split_kernel(
    const float* __restrict__ in, __nv_bfloat16* __restrict__ hi,
    __nv_bfloat16* __restrict__ lo, int n4)
{
    int i = blockIdx.x * blockDim.x + threadIdx.x;
    if (i >= n4) return;
    float4 v = ((const float4*)in)[i];
    __nv_bfloat162 h0, l0, h1, l1;
    split2(v.x, v.y, &h0, &l0);
    split2(v.z, v.w, &h1, &l1);
    ((__nv_bfloat162*)hi)[2 * i]     = h0;
    ((__nv_bfloat162*)hi)[2 * i + 1] = h1;
    ((__nv_bfloat162*)lo)[2 * i]     = l0;
    ((__nv_bfloat162*)lo)[2 * i + 1] = l1;
}

// ---------------- RMSNorm * w * gamma + beta -> bf16 hi/lo ----------------
__global__ void __launch_bounds__(256) rmsnorm_affine_kernel(
    const float* __restrict__ x, const float* __restrict__ w,
    const float* __restrict__ gamma, const float* __restrict__ beta,
    __nv_bfloat16* __restrict__ ohi, __nv_bfloat16* __restrict__ olo)
{
    const int row = blockIdx.x;
    const float4* xr = (const float4*)(x + (size_t)row * DD);
    const int t = threadIdx.x;

    float4 v0 = xr[t];
    float4 v1 = xr[t + 256];
    float ss = v0.x*v0.x + v0.y*v0.y + v0.z*v0.z + v0.w*v0.w
             + v1.x*v1.x + v1.y*v1.y + v1.z*v1.z + v1.w*v1.w;
    #pragma unroll
    for (int d = 16; d; d >>= 1) ss += __shfl_xor_sync(0xffffffffu, ss, d);
    __shared__ float red[8];
    if ((t & 31) == 0) red[t >> 5] = ss;
    __syncthreads();
    float tot = red[0] + red[1] + red[2] + red[3] + red[4] + red[5] + red[6] + red[7];
    const float inv = rsqrtf(tot * (1.0f / DD) + 1.1920929e-07f);

    const float4* w4 = (const float4*)w;
    const float4* g4 = (const float4*)gamma;
    const float4* b4 = (const float4*)beta;
    __nv_bfloat162* oh = (__nv_bfloat162*)(ohi + (size_t)row * DD);
    __nv_bfloat162* ol = (__nv_bfloat162*)(olo + (size_t)row * DD);
    #pragma unroll
    for (int c = 0; c < 2; ++c) {
        int i = t + c * 256;
        float4 xv = (c == 0) ? v0 : v1;
        float4 wv = w4[i], gv = g4[i], bv = b4[i];
        float4 o;
        o.x = xv.x * inv * wv.x * gv.x + bv.x;
        o.y = xv.y * inv * wv.y * gv.y + bv.y;
        o.z = xv.z * inv * wv.z * gv.z + bv.z;
        o.w = xv.w * inv * wv.w * gv.w + bv.w;
        __nv_bfloat162 h0, l0, h1, l1;
        split2(o.x, o.y, &h0, &l0);
        split2(o.z, o.w, &h1, &l1);
        oh[2 * i] = h0; oh[2 * i + 1] = h1;
        ol[2 * i] = l0; ol[2 * i + 1] = l1;
    }
}

// ======================= mma.sync GEMM =======================
// C[M,N] = A[M,K] @ B[N,K]^T. CTA 128x128, BK=32, 8 warps (2Mx4N), warp 64x32.
// 4-stage cp.async ring, ONE barrier per iteration, hoisted fragment loads.
// Output: fp32 (+res) or bf16 hi/lo split.
#define BKC 32
#define STG 4
#define STAGE_B 32768
#define OFF_AH 0
#define OFF_AL 8192
#define OFF_BH 16384
#define OFF_BL 24576
#define GEMM_SMEM (STG * STAGE_B)

// swizzled byte offset for (row, 16B-unit u) in a [128][32]bf16 tile (64B rows)
#define SWZ(r_, u_) ((uint32_t)(r_) * 64u + ((((uint32_t)(u_)) ^ (((uint32_t)(r_) >> 1) & 3u)) << 4))

template<bool RES, bool SPLIT>
__global__ void __launch_bounds__(256) gemm_mma_kernel(
    const __nv_bfloat16* __restrict__ Ahi, const __nv_bfloat16* __restrict__ Alo,
    const __nv_bfloat16* __restrict__ Bhi, const __nv_bfloat16* __restrict__ Blo,
    const float* __restrict__ res, float* __restrict__ C,
    __nv_bfloat16* __restrict__ Chi, __nv_bfloat16* __restrict__ Clo,
    int N, int K)
{
    extern __shared__ char smraw[];
    const uint32_t sb = smem_u32(smraw);
    const int tid  = threadIdx.x;
    const int lane = tid & 31;
    const int warp = tid >> 5;
    const int wm = warp >> 2, wn = warp & 3;
    const int row0 = blockIdx.y << 7;
    const int col0 = blockIdx.x << 7;

    const int lr = tid >> 2, lu = tid & 3;
    const uint32_t wsw0 = SWZ(lr, lu);
    const uint32_t wsw1 = SWZ(lr + 64, lu);
    const size_t rK64 = (size_t)64 * K;
    const __nv_bfloat16* gAh = Ahi + (size_t)(row0 + lr) * K + lu * 8;
    const __nv_bfloat16* gAl = Alo + (size_t)(row0 + lr) * K + lu * 8;
    const __nv_bfloat16* gBh = Bhi + (size_t)(col0 + lr) * K + lu * 8;
    const __nv_bfloat16* gBl = Blo + (size_t)(col0 + lr) * K + lu * 8;

#define LOAD_STAGE(kt_, st_) do {                                   \
    uint32_t b_ = sb + (uint32_t)(st_) * STAGE_B;                   \
    size_t ko_ = (size_t)(kt_) * BKC;                               \
    cp_async16(b_ + OFF_AH + wsw0, gAh + ko_);                      \
    cp_async16(b_ + OFF_AH + wsw1, gAh + rK64 + ko_);               \
    cp_async16(b_ + OFF_AL + wsw0, gAl + ko_);                      \
    cp_async16(b_ + OFF_AL + wsw1, gAl + rK64 + ko_);               \
    cp_async16(b_ + OFF_BH + wsw0, gBh + ko_);                      \
    cp_async16(b_ + OFF_BH + wsw1, gBh + rK64 + ko_);               \
    cp_async16(b_ + OFF_BL + wsw0, gBl + ko_);                      \
    cp_async16(b_ + OFF_BL + wsw1, gBl + rK64 + ko_);               \
    cp_commit();                                                    \
} while (0)

    const int m8 = lane >> 3;
    uint32_t offA[4][2], offB[2][2];
    #pragma unroll
    for (int i = 0; i < 4; ++i)
        #pragma unroll
        for (int kc = 0; kc < 2; ++kc) {
            int rowa = wm * 64 + i * 16 + ((m8 & 1) << 3) + (lane & 7);
            int ua = kc * 2 + (m8 >> 1);
            offA[i][kc] = SWZ(rowa, ua);
        }
    #pragma unroll
    for (int j = 0; j < 2; ++j)
        #pragma unroll
        for (int kc = 0; kc < 2; ++kc) {
            int nb = wn * 32 + j * 16 + ((m8 >> 1) << 3) + (lane & 7);
            int ub = kc * 2 + (m8 & 1);
            offB[j][kc] = SWZ(nb, ub);
        }

    float acc[4][4][4];
    #pragma unroll
    for (int i = 0; i < 4; ++i)
        #pragma unroll
        for (int j = 0; j < 4; ++j)
            #pragma unroll
            for (int r = 0; r < 4; ++r) acc[i][j][r] = 0.f;

    const int nk = K / BKC;

    LOAD_STAGE(0, 0);
    LOAD_STAGE(1, 1);
    LOAD_STAGE(2, 2);

    for (int kt = 0; kt < nk; ++kt) {
        const int rem = nk - 1 - kt;
        if (rem >= 2)      CP_WAIT(2);
        else if (rem == 1) CP_WAIT(1);
        else               CP_WAIT(0);
        __syncthreads();
        if (kt + 3 < nk) LOAD_STAGE(kt + 3, (kt + 3) & 3);

        const uint32_t base = sb + (uint32_t)(kt & 3) * STAGE_B;
        uint32_t ah[2][4][4], al[2][4][4], bh[2][2][4], bl[2][2][4];
        #pragma unroll
        for (int kc = 0; kc < 2; ++kc) {
            #pragma unroll
            for (int i = 0; i < 4; ++i) {
                ldsm4(ah[kc][i], base + OFF_AH + offA[i][kc]);
                ldsm4(al[kc][i], base + OFF_AL + offA[i][kc]);
            }
            #pragma unroll
            for (int j = 0; j < 2; ++j) {
                ldsm4(bh[kc][j], base + OFF_BH + offB[j][kc]);
                ldsm4(bl[kc][j], base + OFF_BL + offB[j][kc]);
            }
        }
        #pragma unroll
        for (int kc = 0; kc < 2; ++kc)
            #pragma unroll
            for (int i = 0; i < 4; ++i)
                #pragma unroll
                for (int jf = 0; jf < 4; ++jf) {
                    const uint32_t* bhp = &bh[kc][jf >> 1][(jf & 1) * 2];
                    const uint32_t* blp = &bl[kc][jf >> 1][(jf & 1) * 2];
                    mma_bf16(acc[i][jf], ah[kc][i], bhp);
                    mma_bf16(acc[i][jf], ah[kc][i], blp);
                    mma_bf16(acc[i][jf], al[kc][i], bhp);
                }
    }

    // ---- epilogue ----
    const int er = lane >> 2;
    const int ec = (lane & 3) * 2;
    #pragma unroll
    for (int i = 0; i < 4; ++i) {
        const int grow = row0 + wm * 64 + i * 16 + er;
        #pragma unroll
        for (int jf = 0; jf < 4; ++jf) {
            const int gcol = col0 + wn * 32 + jf * 8 + ec;
            float v00 = acc[i][jf][0], v01 = acc[i][jf][1];
            float v10 = acc[i][jf][2], v11 = acc[i][jf][3];
            if (SPLIT) {
                uint32_t h, l;
                split_pack(v00, v01, &h, &l);
                *(uint32_t*)(Chi + (size_t)grow * N + gcol) = h;
                *(uint32_t*)(Clo + (size_t)grow * N + gcol) = l;
                split_pack(v10, v11, &h, &l);
                *(uint32_t*)(Chi + (size_t)(grow + 8) * N + gcol) = h;
                *(uint32_t*)(Clo + (size_t)(grow + 8) * N + gcol) = l;
            } else {
                if (RES) {
                    float2 r0 = *(const float2*)(res + (size_t)grow * N + gcol);
                    float2 r1 = *(const float2*)(res + (size_t)(grow + 8) * N + gcol);
                    v00 += r0.x; v01 += r0.y; v10 += r1.x; v11 += r1.y;
                }
                *(float2*)(C + (size_t)grow * N + gcol) = make_float2(v00, v01);
                *(float2*)(C + (size_t)(grow + 8) * N + gcol) = make_float2(v10, v11);
            }
        }
    }
#undef LOAD_STAGE
}

// ======================= tensor-core causal flash attention =======================
// BR=128 (8 warps x m16), BC=64, HD=128. Q/K/V bf16 hi/lo, 3-term mma everywhere.
// smem: Qh 32K | Ql 32K | 2 stages x (Kh,Kl,Vh,Vl 16K each = 64K) = 192KB.
#define ATT_SMEM 196608
// [128]bf16 rows = 256B = 16 units of 16B; swizzle u ^ (r&7)
#define SWA(r_, u_) ((uint32_t)(r_) * 256u + ((((uint32_t)(u_)) ^ ((uint32_t)(r_) & 7u)) << 4))

__global__ void __launch_bounds__(256) flash_attn_mma_kernel(
    const __nv_bfloat16* __restrict__ qkvh, const __nv_bfloat16* __restrict__ qkvl,
    __nv_bfloat16* __restrict__ ohi, __nv_bfloat16* __restrict__ olo)
{
    const int qt = blockIdx.x;           // q tile of 128 rows
    const int bh = blockIdx.y;
    const int b = bh >> 4, h = bh & 15;
    extern __shared__ char smraw[];
    const uint32_t sb = smem_u32(smraw);
    const uint32_t sQh = sb, sQl = sb + 32768;

    const int tid = threadIdx.x;
    const int lane = tid & 31;
    const int w = tid >> 5;
    const int bT = b * TT;
    const int hO = h * HD;
    const float sc = 0.08838834764831845f;   // 1/sqrt(128)

    // ---- load Q (128 rows x 16 units, hi+lo) ----
    {
        const int r = tid >> 1, ub = (tid & 1) * 8;
        const __nv_bfloat16* qh_row = qkvh + (size_t)(bT + qt * 128 + r) * QKVW + hO;
        const __nv_bfloat16* ql_row = qkvl + (size_t)(bT + qt * 128 + r) * QKVW + hO;
        #pragma unroll
        for (int i = 0; i < 8; ++i) {
            int u = ub + i;
            cp_async16(sQh + SWA(r, u), qh_row + u * 8);
            cp_async16(sQl + SWA(r, u), ql_row + u * 8);
        }
    }
    // ---- KV tile loader ----
    const int kvr = tid >> 2, kvu = (tid & 3) * 4;
#define LOAD_KV(jt_, s_) do {                                                        \
    uint32_t bb_ = sb + 65536u + (uint32_t)(s_) * 65536u;                            \
    size_t tok_ = (size_t)(bT + (jt_) * 64 + kvr) * QKVW + hO;                       \
    _Pragma("unroll")                                                                \
    for (int i_ = 0; i_ < 4; ++i_) {                                                 \
        int u_ = kvu + i_;                                                           \
        uint32_t so_ = SWA(kvr, u_);                                                 \
        cp_async16(bb_ + so_,          qkvh + tok_ + 2048 + u_ * 8);                 \
        cp_async16(bb_ + 16384u + so_, qkvl + tok_ + 2048 + u_ * 8);                 \
        cp_async16(bb_ + 32768u + so_, qkvh + tok_ + 4096 + u_ * 8);                 \
        cp_async16(bb_ + 49152u + so_, qkvl + tok_ + 4096 + u_ * 8);                 \
    }                                                                                \
} while (0)

    LOAD_KV(0, 0);
    cp_commit();

    // ---- ldsm offsets ----
    uint32_t offQ[8], offKB[4][8], offV[8][4];
    {
        int rq = w * 16 + ((lane >> 3) & 1) * 8 + (lane & 7);
        #pragma unroll
        for (int c = 0; c < 8; ++c) offQ[c] = SWA(rq, 2 * c + (lane >> 4));
        int rk = ((lane >> 4) << 3) + (lane & 7);
        #pragma unroll
        for (int nb = 0; nb < 4; ++nb)
            #pragma unroll
            for (int c = 0; c < 8; ++c)
                offKB[nb][c] = SWA(nb * 16 + rk, 2 * c + ((lane >> 3) & 1));
        int rv = ((lane >> 3) & 1) * 8 + (lane & 7);
        #pragma unroll
        for (int hb = 0; hb < 8; ++hb)
            #pragma unroll
            for (int c2 = 0; c2 < 4; ++c2)
                offV[hb][c2] = SWA(c2 * 16 + rv, hb * 2 + (lane >> 4));
    }

    uint32_t qh[8][4], ql[8][4];
    float Oa[16][4];
    #pragma unroll
    for (int g = 0; g < 16; ++g)
        #pragma unroll
        for (int r = 0; r < 4; ++r) Oa[g][r] = 0.f;
    float m0 = -INFINITY, m1 = -INFINITY, l0 = 0.f, l1 = 0.f;

    const int row0 = qt * 128 + w * 16 + (lane >> 2);
    const int row1 = row0 + 8;
    const int jend = 2 * qt + 1;

    for (int jt = 0; jt <= jend; ++jt) {
        const int s = jt & 1;
        if (jt < jend) { LOAD_KV(jt + 1, s ^ 1); cp_commit(); CP_WAIT(1); }
        else           { CP_WAIT(0); }
        __syncthreads();

        if (jt == 0) {
            #pragma unroll
            for (int c = 0; c < 8; ++c) {
                ldsm4(qh[c], sQh + offQ[c]);
                ldsm4(ql[c], sQl + offQ[c]);
            }
        }

        const uint32_t bK = sb + 65536u + (uint32_t)s * 65536u;
        const uint32_t bKl = bK + 16384u, bVh = bK + 32768u, bVl = bK + 49152u;

        // ---- S = Q K^T (3-term) ----
        float sf[8][4];
        #pragma unroll
        for (int i = 0; i < 8; ++i)
            #pragma unroll
            for (int r = 0; r < 4; ++r) sf[i][r] = 0.f;
        #pragma unroll
        for (int c = 0; c < 8; ++c)
            #pragma unroll
            for (int nb = 0; nb < 4; ++nb) {
                uint32_t kh[4], kl[4];
                ldsm4(kh, bK  + offKB[nb][c]);
                ldsm4(kl, bKl + offKB[nb][c]);
                mma_bf16(sf[nb * 2],     qh[c], kh);
                mma_bf16(sf[nb * 2],     qh[c], kl);
                mma_bf16(sf[nb * 2],     ql[c], kh);
                mma_bf16(sf[nb * 2 + 1], qh[c], kh + 2);
                mma_bf16(sf[nb * 2 + 1], qh[c], kl + 2);
                mma_bf16(sf[nb * 2 + 1], ql[c], kh + 2);
            }

        // ---- causal mask (only near-diagonal tiles) ----
        if (jt * 64 + 63 > qt * 128 + w * 16) {
            const int jb = jt * 64 + (lane & 3) * 2;
            #pragma unroll
            for (int i = 0; i < 8; ++i) {
                int c0 = jb + i * 8;
                if (c0     > row0) sf[i][0] = -INFINITY;
                if (c0 + 1 > row0) sf[i][1] = -INFINITY;
                if (c0     > row1) sf[i][2] = -INFINITY;
                if (c0 + 1 > row1) sf[i][3] = -INFINITY;
            }
        }

        // ---- online softmax (scaled domain) ----
        float mx0 = -INFINITY, mx1 = -INFINITY;
        #pragma unroll
        for (int i = 0; i < 8; ++i) {
            mx0 = fmaxf(mx0, fmaxf(sf[i][0], sf[i][1]));
            mx1 = fmaxf(mx1, fmaxf(sf[i][2], sf[i][3]));
        }
        mx0 *= sc; mx1 *= sc;
        mx0 = fmaxf(mx0, __shfl_xor_sync(0xffffffffu, mx0, 1));
        mx0 = fmaxf(mx0, __shfl_xor_sync(0xffffffffu, mx0, 2));
        mx1 = fmaxf(mx1, __shfl_xor_sync(0xffffffffu, mx1, 1));
        mx1 = fmaxf(mx1, __shfl_xor_sync(0xffffffffu, mx1, 2));
        float mn0 = fmaxf(m0, mx0), mn1 = fmaxf(m1, mx1);
        float al0 = __expf(m0 - mn0), al1 = __expf(m1 - mn1);
        m0 = mn0; m1 = mn1;
        float ps0 = 0.f, ps1 = 0.f;
        #pragma unroll
        for (int i = 0; i < 8; ++i) {
            sf[i][0] = __expf(fmaf(sf[i][0], sc, -m0)); ps0 += sf[i][0];
            sf[i][1] = __expf(fmaf(sf[i][1], sc, -m0)); ps0 += sf[i][1];
            sf[i][2] = __expf(fmaf(sf[i][2], sc, -m1)); ps1 += sf[i][2];
            sf[i][3] = __expf(fmaf(sf[i][3], sc, -m1)); ps1 += sf[i][3];
        }
        ps0 += __shfl_xor_sync(0xffffffffu, ps0, 1);
        ps0 += __shfl_xor_sync(0xffffffffu, ps0, 2);
        ps1 += __shfl_xor_sync(0xffffffffu, ps1, 1);
        ps1 += __shfl_xor_sync(0xffffffffu, ps1, 2);
        l0 = l0 * al0 + ps0; l1 = l1 * al1 + ps1;
        #pragma unroll
        for (int g = 0; g < 16; ++g) {
            Oa[g][0] *= al0; Oa[g][1] *= al0;
            Oa[g][2] *= al1; Oa[g][3] *= al1;
        }

        // ---- P fragments (C->A identity), hi/lo ----
        uint32_t ph[4][4], pl[4][4];
        #pragma unroll
        for (int c2 = 0; c2 < 4; ++c2) {
            split_pack(sf[2 * c2][0],     sf[2 * c2][1],     &ph[c2][0], &pl[c2][0]);
            split_pack(sf[2 * c2][2],     sf[2 * c2][3],     &ph[c2][1], &pl[c2][1]);
            split_pack(sf[2 * c2 + 1][0], sf[2 * c2 + 1][1], &ph[c2][2], &pl[c2][2]);
            split_pack(sf[2 * c2 + 1][2], sf[2 * c2 + 1][3], &ph[c2][3], &pl[c2][3]);
        }

        // ---- O += P V (3-term, V via ldmatrix.trans) ----
        #pragma unroll
        for (int c2 = 0; c2 < 4; ++c2)
            #pragma unroll
            for (int hb = 0; hb < 8; ++hb) {
                uint32_t vh[4], vl[4];
                ldsm4t(vh, bVh + offV[hb][c2]);
                ldsm4t(vl, bVl + offV[hb][c2]);
                mma_bf16(Oa[hb * 2],     ph[c2], vh);
                mma_bf16(Oa[hb * 2],     ph[c2], vl);
                mma_bf16(Oa[hb * 2],     pl[c2], vh);
                mma_bf16(Oa[hb * 2 + 1], ph[c2], vh + 2);
                mma_bf16(Oa[hb * 2 + 1], ph[c2], vl + 2);
                mma_bf16(Oa[hb * 2 + 1], pl[c2], vh + 2);
            }
        __syncthreads();
    }

    // ---- epilogue: O/l -> bf16 hi/lo ----
    const float il0 = 1.0f / l0, il1 = 1.0f / l1;
    const size_t tok0 = (size_t)(bT + row0);
    #pragma unroll
    for (int g = 0; g < 16; ++g) {
        const int col = hO + g * 8 + (lane & 3) * 2;
        uint32_t hi, lo;
        split_pack(Oa[g][0] * il0, Oa[g][1] * il0, &hi, &lo);
        *(uint32_t*)(ohi + tok0 * DD + col) = hi;
        *(uint32_t*)(olo + tok0 * DD + col) = lo;
        split_pack(Oa[g][2] * il1, Oa[g][3] * il1, &hi, &lo);
        *(uint32_t*)(ohi + (tok0 + 8) * DD + col) = hi;
        *(uint32_t*)(olo + (tok0 + 8) * DD + col) = lo;
    }
#undef LOAD_KV
}

// ---------------- silu(gate) * up -> bf16 hi/lo ----------------
__global__ void __launch_bounds__(256) silu_mul_kernel(
    const float* __restrict__ g, const float* __restrict__ u,
    __nv_bfloat16* __restrict__ ohi, __nv_bfloat16* __restrict__ olo, int n4)
{
    int i = blockIdx.x * blockDim.x + threadIdx.x;
    if (i < n4) {
        float4 gv = ((const float4*)g)[i];
        float4 uv = ((const float4*)u)[i];
        float4 r;
        r.x = gv.x / (1.f + __expf(-gv.x)) * uv.x;
        r.y = gv.y / (1.f + __expf(-gv.y)) * uv.y;
        r.z = gv.z / (1.f + __expf(-gv.z)) * uv.z;
        r.w = gv.w / (1.f + __expf(-gv.w)) * uv.w;
        __nv_bfloat162 h0, l0, h1, l1;
        split2(r.x, r.y, &h0, &l0);
        split2(r.z, r.w, &h1, &l1);
        ((__nv_bfloat162*)ohi)[2 * i]     = h0;
        ((__nv_bfloat162*)ohi)[2 * i + 1] = h1;
        ((__nv_bfloat162*)olo)[2 * i]     = l0;
        ((__nv_bfloat162*)olo)[2 * i + 1] = l1;
    }
}

// ---------------- launch ----------------
extern "C" void kernel_launch(void* const* d_in, const int* in_sizes, int n_in,
                              void* d_out, int out_size)
{
    const float* x      = (const float*)d_in[0];
    const float* gamma  = (const float*)d_in[1];
    const float* beta   = (const float*)d_in[2];
    const float* qkv_w  = (const float*)d_in[3];
    const float* o_w    = (const float*)d_in[4];
    const float* gate_w = (const float*)d_in[5];
    const float* up_w   = (const float*)d_in[6];
    const float* down_w = (const float*)d_in[7];
    const float* n1w    = (const float*)d_in[8];
    const float* n2w    = (const float*)d_in[9];
    float* out = (float*)d_out;

    float *x1_, *gate_, *up_;
    __nv_bfloat16 *ahi, *alo, *qkvh, *qkvl;
    __nv_bfloat16 *wqh, *wql, *woh, *wol, *wgh, *wgl, *wuh, *wul, *wdh, *wdl;
    cudaGetSymbolAddress((void**)&x1_,   g_x1);
    cudaGetSymbolAddress((void**)&gate_, g_gate);
    cudaGetSymbolAddress((void**)&up_,   g_up);
    cudaGetSymbolAddress((void**)&ahi,  g_act_hi);
    cudaGetSymbolAddress((void**)&alo,  g_act_lo);
    cudaGetSymbolAddress((void**)&qkvh, g_qkv_hi);
    cudaGetSymbolAddress((void**)&qkvl, g_qkv_lo);
    cudaGetSymbolAddress((void**)&wqh, g_wqkv_hi);  cudaGetSymbolAddress((void**)&wql, g_wqkv_lo);
    cudaGetSymbolAddress((void**)&woh, g_wo_hi);    cudaGetSymbolAddress((void**)&wol, g_wo_lo);
    cudaGetSymbolAddress((void**)&wgh, g_wg_hi);    cudaGetSymbolAddress((void**)&wgl, g_wg_lo);
    cudaGetSymbolAddress((void**)&wuh, g_wu_hi);    cudaGetSymbolAddress((void**)&wul, g_wu_lo);
    cudaGetSymbolAddress((void**)&wdh, g_wd_hi);    cudaGetSymbolAddress((void**)&wdl, g_wd_lo);

    cudaFuncSetAttribute(flash_attn_mma_kernel,
                         cudaFuncAttributeMaxDynamicSharedMemorySize, ATT_SMEM);
    cudaFuncSetAttribute(gemm_mma_kernel<false, false>,
                         cudaFuncAttributeMaxDynamicSharedMemorySize, GEMM_SMEM);
    cudaFuncSetAttribute(gemm_mma_kernel<true, false>,
                         cudaFuncAttributeMaxDynamicSharedMemorySize, GEMM_SMEM);
    cudaFuncSetAttribute(gemm_mma_kernel<false, true>,
                         cudaFuncAttributeMaxDynamicSharedMemorySize, GEMM_SMEM);

    // 0. split weights to bf16 hi/lo
    {
        int n;
        n = QKVW * DD / 4; split_kernel<<<(n + 255) / 256, 256>>>(qkv_w,  wqh, wql, n);
        n = DD * DD / 4;   split_kernel<<<(n + 255) / 256, 256>>>(o_w,    woh, wol, n);
        n = FF * DD / 4;   split_kernel<<<(n + 255) / 256, 256>>>(gate_w, wgh, wgl, n);
        n = FF * DD / 4;   split_kernel<<<(n + 255) / 256, 256>>>(up_w,   wuh, wul, n);
        n = DD * FF / 4;   split_kernel<<<(n + 255) / 256, 256>>>(down_w, wdh, wdl, n);
    }

    // 1. h = rmsnorm(x, n1)*gamma+beta  -> act (bf16 hi/lo)
    rmsnorm_affine_kernel<<<MTOK, 256>>>(x, n1w, gamma, beta, ahi, alo);
    // 2. qkv = h @ qkv_w^T -> bf16 hi/lo directly
    gemm_mma_kernel<false, true><<<dim3(QKVW / 128, MTOK / 128), 256, GEMM_SMEM>>>(
        ahi, alo, wqh, wql, nullptr, nullptr, qkvh, qkvl, QKVW, DD);
    // 3. attention (tensor cores) -> act (bf16 hi/lo)
    flash_attn_mma_kernel<<<dim3(TT / 128, BB * HH), 256, ATT_SMEM>>>(qkvh, qkvl, ahi, alo);
    // 4. x1 = x + attn @ o_w^T
    gemm_mma_kernel<true, false><<<dim3(DD / 128, MTOK / 128), 256, GEMM_SMEM>>>(
        ahi, alo, woh, wol, x, x1_, nullptr, nullptr, DD, DD);
    // 5. h = rmsnorm(x1, n2)*gamma+beta -> act
    rmsnorm_affine_kernel<<<MTOK, 256>>>(x1_, n2w, gamma, beta, ahi, alo);
    // 6/7. gate, up (fp32 out)
    gemm_mma_kernel<false, false><<<dim3(FF / 128, MTOK / 128), 256, GEMM_SMEM>>>(
        ahi, alo, wgh, wgl, nullptr, gate_, nullptr, nullptr, FF, DD);
    gemm_mma_kernel<false, false><<<dim3(FF / 128, MTOK / 128), 256, GEMM_SMEM>>>(
        ahi, alo, wuh, wul, nullptr, up_, nullptr, nullptr, FF, DD);
    // 8. ff = silu(gate)*up -> act (bf16 hi/lo, K=FF)
    silu_mul_kernel<<<(MTOK * FF / 4 + 255) / 256, 256>>>(gate_, up_, ahi, alo, MTOK * FF / 4);
    // 9. out = x1 + ff @ down_w^T
    gemm_mma_kernel<true, false><<<dim3(DD / 128, MTOK / 128), 256, GEMM_SMEM>>>(
        ahi, alo, wdh, wdl, x1_, out, nullptr, nullptr, DD, FF);
}